// round 12
// baseline (speedup 1.0000x reference)
#include <cuda_runtime.h>
#include <cstdint>

// AdditiveModel on GB300 — R11: R8 compute structure; x staged at j granularity
// with 16B cp.async chunks (8 instrs x 8 lines per j = half of R8's staging
// wavefronts; each x line touched 2x instead of 4x). Ring of 2 j-slots,
// row layout alternating pad 20/16 (row r at (r>>1)*36+(r&1)*20 floats,
// verified overlap-free, 16B-aligned chunks, 2-way read conflicts).
// Smem 109.6KB -> 112KB -> 2 CTAs; 128 regs. Compute identical to R8.
//
// Math (folded into smem-staged weights):
//   sigmoid(z) = 0.5*tanh(0.5 z) + 0.5
//   conv1: a = 0.5*(W1m x + b1); t = tanh(a)
//   conv2: c = (0.25 W2) t + (0.25*rowsum(W2) + 0.5 b2); t2 = tanh(c)
//   out   = sum 0.5*w3*t2 + (b3 + 0.5*sum w3)

#define NV 16
#define BB 32768
typedef unsigned long long ull;

__device__ __forceinline__ ull dup2(float x) {
    ull r; asm("mov.b64 %0, {%1, %1};" : "=l"(r) : "f"(x)); return r;
}
__device__ __forceinline__ ull pack2(float lo, float hi) {
    ull r; asm("mov.b64 %0, {%1, %2};" : "=l"(r) : "f"(lo), "f"(hi)); return r;
}
__device__ __forceinline__ void unpack2(ull v, float& lo, float& hi) {
    asm("mov.b64 {%0, %1}, %2;" : "=f"(lo), "=f"(hi) : "l"(v));
}
__device__ __forceinline__ void fma2(ull& d, ull a, ull b) {
    asm("fma.rn.f32x2 %0, %1, %2, %0;" : "+l"(d) : "l"(a), "l"(b));
}
__device__ __forceinline__ float tanh_fast(float x) {
    float t; asm("tanh.approx.f32 %0, %1;" : "=f"(t) : "f"(x)); return t;
}

// dynamic smem (floats):
//   sX[8 warps][2 j-slots][1152]  73728 B  (64 rows/slot, alt pad 20/16)
//   sW1p[2048] ull  16384 B   ([j][l][hp] pairs, 0.5*mask folded)
//   sW2p[2048] ull  16384 B   ([j][h][kp] pairs, 0.25 folded)
//   sB1p/sB2p/sW3p[128] ull   3072 B
//   sOutC 16 B                  total 109584 B -> 112KB -> 2 CTAs/SM
#define SMEM_BYTES (73728 + 16384 + 16384 + 1024 + 1024 + 1024 + 16)

__global__ __launch_bounds__(256, 2)
void additive_model_kernel(const float* __restrict__ x,
                           const int*   __restrict__ causal,
                           const float* __restrict__ W1,
                           const float* __restrict__ b1,
                           const float* __restrict__ W2,
                           const float* __restrict__ b2,
                           const float* __restrict__ W3,
                           const float* __restrict__ b3,
                           float* __restrict__ out)
{
    extern __shared__ float smem[];
    float* sXall = smem;                          // 8 * 2 * 1152 = 18432 floats
    ull*   sW1p  = (ull*)(smem + 18432);          // 2048
    ull*   sW2p  = sW1p + 2048;
    ull*   sB1p  = sW2p + 2048;
    ull*   sB2p  = sB1p + 128;
    ull*   sW3p  = sB2p + 128;
    float* sOutC = (float*)(sW3p + 128);

    const int v    = blockIdx.x & 15;
    const int bblk = blockIdx.x >> 4;
    const int tid  = threadIdx.x;
    const int wid  = tid >> 5;
    const int lane = tid & 31;
    const int g0   = v * 16;

    // ---- stage weights (pre-paired, scales folded) ----
    #pragma unroll
    for (int i = 0; i < 8; ++i) {
        const int e  = tid + i * 256;          // 0..2047
        const int j  = e >> 7;
        const int m2 = (e >> 3) & 15;          // l for W1, h for W2
        const int p  = e & 7;                  // hp / kp
        const int g  = g0 + j;
        const float ms = (causal[g * 16 + m2] != 0) ? 0.5f : 0.0f;
        sW1p[e] = pack2(ms * W1[(g * 16 + 2 * p) * 16 + m2],
                        ms * W1[(g * 16 + 2 * p + 1) * 16 + m2]);
        sW2p[e] = pack2(0.25f * W2[g * 256 + (2 * p) * 16 + m2],
                        0.25f * W2[g * 256 + (2 * p + 1) * 16 + m2]);
    }
    if (tid < 128) {
        const int j = tid >> 3, p = tid & 7;
        const int g = g0 + j;
        sB1p[tid] = pack2(0.5f * b1[g * 16 + 2 * p], 0.5f * b1[g * 16 + 2 * p + 1]);
        float s0 = 0.f, s1 = 0.f;
        #pragma unroll
        for (int h = 0; h < 16; ++h) {
            s0 += W2[g * 256 + (2 * p) * 16 + h];
            s1 += W2[g * 256 + (2 * p + 1) * 16 + h];
        }
        sB2p[tid] = pack2(0.25f * s0 + 0.5f * b2[g * 16 + 2 * p],
                          0.25f * s1 + 0.5f * b2[g * 16 + 2 * p + 1]);
        sW3p[tid] = pack2(0.5f * W3[v * 256 + j * 16 + 2 * p],
                          0.5f * W3[v * 256 + j * 16 + 2 * p + 1]);
    }
    if (tid == 0) {
        float c = b3[v];
        #pragma unroll 1
        for (int m = 0; m < 256; ++m) c += 0.5f * W3[v * 256 + m];
        *sOutC = c;
    }
    __syncthreads();   // only CTA barrier

    // ---- warp-private x staging: ring of 2 j-slots, 16B cp.async chunks ----
    // warp owns 64 batch rows. Per instr: lane = srow(0..7) x chunk(0..3 of 16B);
    // _i = row group (rows srow + 8*_i) -> 8 lines/instr, 64B consumed each.
    // Row r stored at float offset (r>>1)*36 + (r&1)*20 (overlap-free, 16B-aligned).
    const float* xw = x + (size_t)(bblk * 512 + wid * 64) * 4096 + g0 * 16;
    float* bufW = sXall + wid * 2304;      // 2 slots * 1152 floats

    const int srow = lane >> 2;            // 0..7
    const int chk  = lane & 3;             // 16B chunk within the 16-float row
    const uint32_t dbase = (uint32_t)__cvta_generic_to_shared(
                               bufW + (srow >> 1) * 36 + (srow & 1) * 20 + chk * 4);
    const float* xsrc = xw + (size_t)srow * 4096 + chk * 4;

    #define STAGE_J(j_)                                                               \
        do {                                                                          \
            const uint32_t _d = dbase + ((j_) & 1) * 4608;   /* slot = 1152 fl */     \
            const float*   _s = xsrc + (j_) * 16;                                     \
            _Pragma("unroll")                                                         \
            for (int _i = 0; _i < 8; ++_i) {                                          \
                asm volatile("cp.async.ca.shared.global [%0], [%1], 16;"              \
                             :: "r"(_d + _i * 576),           /* 8 rows = 144 fl */   \
                                "l"(_s + (size_t)_i * 32768)  /* 8 rows of x    */ ); \
            }                                                                         \
            asm volatile("cp.async.commit_group;");                                   \
        } while (0)

    // prologue: stage j=0 and j=1
    STAGE_J(0);
    STAGE_J(1);

    // this thread's read rows: lane and lane+32 (offset +576 floats)
    const int roff = (lane >> 1) * 36 + (lane & 1) * 20;

    ull sp0 = 0ull, sp1 = 0ull;

    #pragma unroll 1
    for (int j = 0; j < 16; ++j) {
        // in flight at top: stage(j) [maybe done], stage(j+1)
        if (j < 15) { asm volatile("cp.async.wait_group 1;" ::: "memory"); }
        else        { asm volatile("cp.async.wait_group 0;" ::: "memory"); }
        __syncwarp();

        ull a0[8], a1[8];
        #pragma unroll
        for (int hp = 0; hp < 8; ++hp) { a0[hp] = sB1p[j * 8 + hp]; a1[hp] = a0[hp]; }

        const float* xslot = bufW + (j & 1) * 1152;
        const float* xb0 = xslot + roff;
        const float* xb1 = xb0 + 576;      // row lane+32

        const ulonglong2* w1 = (const ulonglong2*)(sW1p + j * 128);
        #pragma unroll
        for (int l2 = 0; l2 < 8; ++l2) {
            const float2 xa = *(const float2*)(xb0 + l2 * 2);
            const float2 xb = *(const float2*)(xb1 + l2 * 2);
            ulonglong2 p0 = w1[l2 * 8 + 0], p1 = w1[l2 * 8 + 1],
                       p2 = w1[l2 * 8 + 2], p3 = w1[l2 * 8 + 3];
            ull da = dup2(xa.x), db = dup2(xb.x);
            fma2(a0[0], p0.x, da); fma2(a1[0], p0.x, db);
            fma2(a0[1], p0.y, da); fma2(a1[1], p0.y, db);
            fma2(a0[2], p1.x, da); fma2(a1[2], p1.x, db);
            fma2(a0[3], p1.y, da); fma2(a1[3], p1.y, db);
            fma2(a0[4], p2.x, da); fma2(a1[4], p2.x, db);
            fma2(a0[5], p2.y, da); fma2(a1[5], p2.y, db);
            fma2(a0[6], p3.x, da); fma2(a1[6], p3.x, db);
            fma2(a0[7], p3.y, da); fma2(a1[7], p3.y, db);
            p0 = w1[l2 * 8 + 4]; p1 = w1[l2 * 8 + 5];
            p2 = w1[l2 * 8 + 6]; p3 = w1[l2 * 8 + 7];
            da = dup2(xa.y); db = dup2(xb.y);
            fma2(a0[0], p0.x, da); fma2(a1[0], p0.x, db);
            fma2(a0[1], p0.y, da); fma2(a1[1], p0.y, db);
            fma2(a0[2], p1.x, da); fma2(a1[2], p1.x, db);
            fma2(a0[3], p1.y, da); fma2(a1[3], p1.y, db);
            fma2(a0[4], p2.x, da); fma2(a1[4], p2.x, db);
            fma2(a0[5], p2.y, da); fma2(a1[5], p2.y, db);
            fma2(a0[6], p3.x, da); fma2(a1[6], p3.x, db);
            fma2(a0[7], p3.y, da); fma2(a1[7], p3.y, db);
        }

        // slot (j&1) is free after conv1: prefetch j+2 into it.
        // cover = tanh/conv2/epi(j) + all of iter j+1
        if (j < 14) STAGE_J(j + 2);

        // ---- tanh in place: a[] becomes packed tanh pairs ----
        #pragma unroll
        for (int hp = 0; hp < 8; ++hp) {
            float lo, hi;
            unpack2(a0[hp], lo, hi); a0[hp] = pack2(tanh_fast(lo), tanh_fast(hi));
            unpack2(a1[hp], lo, hi); a1[hp] = pack2(tanh_fast(lo), tanh_fast(hi));
        }

        // ---- conv2: c = (0.25 W2) t + c0 ----
        ull c0[8], c1[8];
        #pragma unroll
        for (int kp = 0; kp < 8; ++kp) { c0[kp] = sB2p[j * 8 + kp]; c1[kp] = c0[kp]; }

        const ulonglong2* w2 = (const ulonglong2*)(sW2p + j * 128);
        #pragma unroll
        for (int hp = 0; hp < 8; ++hp) {
            float s0lo, s0hi, s1lo, s1hi;
            unpack2(a0[hp], s0lo, s0hi);
            unpack2(a1[hp], s1lo, s1hi);
            {   // h = 2*hp
                const int h = 2 * hp;
                const ulonglong2 q0 = w2[h * 4 + 0], q1 = w2[h * 4 + 1],
                                 q2 = w2[h * 4 + 2], q3 = w2[h * 4 + 3];
                const ull da = dup2(s0lo), db = dup2(s1lo);
                fma2(c0[0], q0.x, da); fma2(c1[0], q0.x, db);
                fma2(c0[1], q0.y, da); fma2(c1[1], q0.y, db);
                fma2(c0[2], q1.x, da); fma2(c1[2], q1.x, db);
                fma2(c0[3], q1.y, da); fma2(c1[3], q1.y, db);
                fma2(c0[4], q2.x, da); fma2(c1[4], q2.x, db);
                fma2(c0[5], q2.y, da); fma2(c1[5], q2.y, db);
                fma2(c0[6], q3.x, da); fma2(c1[6], q3.x, db);
                fma2(c0[7], q3.y, da); fma2(c1[7], q3.y, db);
            }
            {   // h = 2*hp + 1
                const int h = 2 * hp + 1;
                const ulonglong2 q0 = w2[h * 4 + 0], q1 = w2[h * 4 + 1],
                                 q2 = w2[h * 4 + 2], q3 = w2[h * 4 + 3];
                const ull da = dup2(s0hi), db = dup2(s1hi);
                fma2(c0[0], q0.x, da); fma2(c1[0], q0.x, db);
                fma2(c0[1], q0.y, da); fma2(c1[1], q0.y, db);
                fma2(c0[2], q1.x, da); fma2(c1[2], q1.x, db);
                fma2(c0[3], q1.y, da); fma2(c1[3], q1.y, db);
                fma2(c0[4], q2.x, da); fma2(c1[4], q2.x, db);
                fma2(c0[5], q2.y, da); fma2(c1[5], q2.y, db);
                fma2(c0[6], q3.x, da); fma2(c1[6], q3.x, db);
                fma2(c0[7], q3.y, da); fma2(c1[7], q3.y, db);
            }
        }

        // ---- epilogue: sp += (0.5 w3) * tanh(c) ----
        #pragma unroll
        for (int kp = 0; kp < 8; ++kp) {
            const ull w3 = sW3p[j * 8 + kp];
            float lo, hi;
            unpack2(c0[kp], lo, hi);
            fma2(sp0, w3, pack2(tanh_fast(lo), tanh_fast(hi)));
            unpack2(c1[kp], lo, hi);
            fma2(sp1, w3, pack2(tanh_fast(lo), tanh_fast(hi)));
        }
    }
    #undef STAGE_J

    const float outC = *sOutC;
    const int b0 = bblk * 512 + wid * 64 + lane;
    float lo, hi;
    unpack2(sp0, lo, hi);
    out[(size_t)b0 * NV + v] = lo + hi + outC;
    unpack2(sp1, lo, hi);
    out[(size_t)(b0 + 32) * NV + v] = lo + hi + outC;
}

extern "C" void kernel_launch(void* const* d_in, const int* in_sizes, int n_in,
                              void* d_out, int out_size)
{
    const float* x      = (const float*)d_in[0];
    const int*   causal = (const int*)  d_in[1];
    const float* W1     = (const float*)d_in[2];
    const float* b1     = (const float*)d_in[3];
    const float* W2     = (const float*)d_in[4];
    const float* b2     = (const float*)d_in[5];
    const float* W3     = (const float*)d_in[6];
    const float* b3     = (const float*)d_in[7];
    float* out = (float*)d_out;

    static int configured = 0;
    if (!configured) {
        cudaFuncSetAttribute(additive_model_kernel,
                             cudaFuncAttributeMaxDynamicSharedMemorySize, SMEM_BYTES);
        configured = 1;
    }

    dim3 grid((BB / 512) * NV);   // 64 batch blocks * 16 variables = 1024 CTAs
    additive_model_kernel<<<grid, 256, SMEM_BYTES>>>(x, causal, W1, b1, W2, b2, W3, b3, out);
}

// round 13
// speedup vs baseline: 1.1872x; 1.1872x over previous
#include <cuda_runtime.h>
#include <cstdint>

// AdditiveModel on GB300 — R12: move conv1/conv2 onto tensor pipe via
// mma.sync.m16n8k8.tf32 (register-resident, no TMEM). Per-warp per-j:
// 32 HMMA replace 512 fma2. Activations tanh'd in C-fragment registers;
// C->A fragment conversion via width-4 shuffles. Weights tf32(rna)-rounded
// at staging; x tf32(rna)-rounded at load. Same sigmoid folding as R8.
//
//   sigmoid(z) = 0.5*tanh(0.5 z) + 0.5
//   conv1: C1 = x @ (0.5*mask*W1)^T + 0.5 b1 ; t1 = tanh(C1)
//   conv2: C2 = t1 @ (0.25*W2)^T + (0.25*rowsum(W2)+0.5 b2) ; t2 = tanh(C2)
//   out   = sum 0.5*w3*t2 + (b3 + 0.5*sum w3)

#define NV 16
#define BB 32768

__device__ __forceinline__ float tanh_fast(float x) {
    float t; asm("tanh.approx.f32 %0, %1;" : "=f"(t) : "f"(x)); return t;
}
__device__ __forceinline__ uint32_t f2tf32(float x) {
    uint32_t r; asm("cvt.rna.tf32.f32 %0, %1;" : "=r"(r) : "f"(x)); return r;
}
__device__ __forceinline__ void mma_tf32(float* d,
                                         uint32_t a0, uint32_t a1, uint32_t a2, uint32_t a3,
                                         uint32_t b0, uint32_t b1) {
    asm("mma.sync.aligned.m16n8k8.row.col.f32.tf32.tf32.f32 "
        "{%0,%1,%2,%3}, {%4,%5,%6,%7}, {%8,%9}, {%0,%1,%2,%3};"
        : "+f"(d[0]), "+f"(d[1]), "+f"(d[2]), "+f"(d[3])
        : "r"(a0), "r"(a1), "r"(a2), "r"(a3), "r"(b0), "r"(b1));
}

// dynamic smem (floats):
//   sX [8 warps][2 slots][64 rows][18]   73728 B  (pitch-18 rows)
//   sW1 [16 j][16 l][16 h]  tf32 bits    16384 B  (0.5*mask folded, B-frag source)
//   sW2t[16 j][16 h][16 k]  tf32 bits    16384 B  (0.25 folded, transposed)
//   sB1/sB2/sW3 [16 j][16]                3072 B
//   sOutC                                   16 B   total 109584 -> 112KB -> 2 CTAs
#define SMEM_BYTES (73728 + 16384 + 16384 + 1024 + 1024 + 1024 + 16)

__global__ __launch_bounds__(256, 2)
void additive_model_kernel(const float* __restrict__ x,
                           const int*   __restrict__ causal,
                           const float* __restrict__ W1,
                           const float* __restrict__ b1,
                           const float* __restrict__ W2,
                           const float* __restrict__ b2,
                           const float* __restrict__ W3,
                           const float* __restrict__ b3,
                           float* __restrict__ out)
{
    extern __shared__ float smem[];
    float*    sX    = smem;                      // 18432 floats
    uint32_t* sW1u  = (uint32_t*)(smem + 18432); // 4096
    uint32_t* sW2u  = sW1u + 4096;               // 4096
    float*    sB1   = (float*)(sW2u + 4096);     // 256
    float*    sB2   = sB1 + 256;
    float*    sW3   = sB2 + 256;
    float*    sOutC = sW3 + 256;

    const int v    = blockIdx.x & 15;
    const int bblk = blockIdx.x >> 4;
    const int tid  = threadIdx.x;
    const int wid  = tid >> 5;
    const int lane = tid & 31;
    const int r    = lane >> 2;   // 0..7
    const int c    = lane & 3;    // 0..3
    const int g0   = v * 16;

    // ---- stage weights (tf32-rounded, scales/mask folded) ----
    #pragma unroll
    for (int i = 0; i < 16; ++i) {
        const int e = tid + i * 256;           // 0..4095
        const int j = e >> 8;
        const int a = (e >> 4) & 15;           // l for W1, h for W2t
        const int b = e & 15;                  // h for W1, k for W2t
        const int g = g0 + j;
        const float ms = (causal[g * 16 + a] != 0) ? 0.5f : 0.0f;
        sW1u[e] = f2tf32(ms * W1[(g * 16 + b) * 16 + a]);       // [j][l][h] = 0.5*mask*W1[h][l]
        sW2u[e] = f2tf32(0.25f * W2[g * 256 + b * 16 + a]);     // [j][h][k] = 0.25*W2[k][h]
    }
    {   // biases + w3 (256 threads exactly cover 16j x 16)
        const int j = tid >> 4, q = tid & 15;
        const int g = g0 + j;
        sB1[tid] = 0.5f * b1[g * 16 + q];
        float s0 = 0.f;
        #pragma unroll
        for (int h = 0; h < 16; ++h) s0 += W2[g * 256 + q * 16 + h];
        sB2[tid] = 0.25f * s0 + 0.5f * b2[g * 16 + q];
        sW3[tid] = 0.5f * W3[v * 256 + j * 16 + q];
    }
    if (tid == 0) {
        float cc = b3[v];
        #pragma unroll 1
        for (int m = 0; m < 256; ++m) cc += 0.5f * W3[v * 256 + m];
        *sOutC = cc;
    }
    __syncthreads();   // only CTA barrier

    // ---- warp-private x staging: 64 rows x 16 floats per j, pitch 18 ----
    const float* xw = x + (size_t)(bblk * 512 + wid * 64) * 4096 + g0 * 16;
    float* slotB = sX + wid * 2304;        // 2 slots * 1152 floats

    // staging map: per instr i (0..15): rows i*4 + lane>>3, 8B chunk lane&7
    const int srow = lane >> 3;            // 0..3
    const int su   = lane & 7;             // 0..7
    const uint32_t dstage = (uint32_t)__cvta_generic_to_shared(
                                slotB + srow * 18 + su * 2);
    const float* sstage = xw + (size_t)srow * 4096 + su * 2;

    #define STAGE_J(j_)                                                               \
        do {                                                                          \
            const uint32_t _d = dstage + ((j_) & 1) * 4608;                           \
            const float*   _s = sstage + (j_) * 16;                                   \
            _Pragma("unroll")                                                         \
            for (int _i = 0; _i < 16; ++_i) {                                         \
                asm volatile("cp.async.ca.shared.global [%0], [%1], 8;"               \
                             :: "r"(_d + _i * 288),          /* 4 rows = 72 fl */     \
                                "l"(_s + (size_t)_i * 16384) /* 4 rows of x   */ );   \
            }                                                                         \
            asm volatile("cp.async.commit_group;");                                   \
        } while (0)

    STAGE_J(0);
    STAGE_J(1);

    float sp[8];   // [T][rowhalf] accumulators across j
    #pragma unroll
    for (int i = 0; i < 8; ++i) sp[i] = 0.0f;

    #pragma unroll 1
    for (int j = 0; j < 16; ++j) {
        if (j < 15) { asm volatile("cp.async.wait_group 1;" ::: "memory"); }
        else        { asm volatile("cp.async.wait_group 0;" ::: "memory"); }
        __syncwarp();

        const float* xs = slotB + (j & 1) * 1152;

        // ---- load all x A-fragments for this j (4 tiles x 2 k-halves x 4 regs) ----
        uint32_t xa[4][8];
        #pragma unroll
        for (int T = 0; T < 4; ++T) {
            #pragma unroll
            for (int kh = 0; kh < 2; ++kh) {
                const int base = (T * 16 + r) * 18 + kh * 8 + c;
                xa[T][kh * 4 + 0] = f2tf32(xs[base]);
                xa[T][kh * 4 + 1] = f2tf32(xs[base + 8 * 18]);
                xa[T][kh * 4 + 2] = f2tf32(xs[base + 4]);
                xa[T][kh * 4 + 3] = f2tf32(xs[base + 8 * 18 + 4]);
            }
        }

        if (j < 14) STAGE_J(j + 2);   // slot free after x loads

        // ---- weight B-fragments (warp-wide, reused across 4 tiles) ----
        uint32_t w1b[2][2][2], w2b[2][2][2];
        #pragma unroll
        for (int kh = 0; kh < 2; ++kh)
            #pragma unroll
            for (int nh = 0; nh < 2; ++nh) {
                const int o = j * 256 + (kh * 8 + c) * 16 + nh * 8 + r;
                w1b[kh][nh][0] = sW1u[o];
                w1b[kh][nh][1] = sW1u[o + 4 * 16];
                w2b[kh][nh][0] = sW2u[o];
                w2b[kh][nh][1] = sW2u[o + 4 * 16];
            }
        float b1v[2][2], b2v[2][2], w3v[2][2];
        #pragma unroll
        for (int nh = 0; nh < 2; ++nh) {
            b1v[nh][0] = sB1[j * 16 + nh * 8 + 2 * c];
            b1v[nh][1] = sB1[j * 16 + nh * 8 + 2 * c + 1];
            b2v[nh][0] = sB2[j * 16 + nh * 8 + 2 * c];
            b2v[nh][1] = sB2[j * 16 + nh * 8 + 2 * c + 1];
            w3v[nh][0] = sW3[j * 16 + nh * 8 + 2 * c];
            w3v[nh][1] = sW3[j * 16 + nh * 8 + 2 * c + 1];
        }

        // ---- per 16-batch tile: conv1 mma -> tanh -> shuffle -> conv2 mma -> epi ----
        #pragma unroll
        for (int T = 0; T < 4; ++T) {
            float C1[2][4];
            #pragma unroll
            for (int nh = 0; nh < 2; ++nh) {
                C1[nh][0] = b1v[nh][0]; C1[nh][1] = b1v[nh][1];
                C1[nh][2] = b1v[nh][0]; C1[nh][3] = b1v[nh][1];
                mma_tf32(C1[nh], xa[T][0], xa[T][1], xa[T][2], xa[T][3],
                         w1b[0][nh][0], w1b[0][nh][1]);
                mma_tf32(C1[nh], xa[T][4], xa[T][5], xa[T][6], xa[T][7],
                         w1b[1][nh][0], w1b[1][nh][1]);
            }
            float t[2][4];
            #pragma unroll
            for (int nh = 0; nh < 2; ++nh)
                #pragma unroll
                for (int i = 0; i < 4; ++i) t[nh][i] = tanh_fast(C1[nh][i]);

            // C-layout (h = nh*8 + 2c + p) -> A-layout (h = kh*8 + c, c+4) via quad shuffles
            uint32_t a2[2][4];
            const bool p = (c & 1);
            #pragma unroll
            for (int kh = 0; kh < 2; ++kh) {
                const float v0 = __shfl_sync(0xffffffffu, t[kh][0], c >> 1, 4);
                const float v1 = __shfl_sync(0xffffffffu, t[kh][1], c >> 1, 4);
                const float v2 = __shfl_sync(0xffffffffu, t[kh][2], c >> 1, 4);
                const float v3 = __shfl_sync(0xffffffffu, t[kh][3], c >> 1, 4);
                const float v4 = __shfl_sync(0xffffffffu, t[kh][0], (c >> 1) + 2, 4);
                const float v5 = __shfl_sync(0xffffffffu, t[kh][1], (c >> 1) + 2, 4);
                const float v6 = __shfl_sync(0xffffffffu, t[kh][2], (c >> 1) + 2, 4);
                const float v7 = __shfl_sync(0xffffffffu, t[kh][3], (c >> 1) + 2, 4);
                a2[kh][0] = __float_as_uint(p ? v1 : v0);   // (r,    kh*8+c)
                a2[kh][1] = __float_as_uint(p ? v3 : v2);   // (r+8,  kh*8+c)
                a2[kh][2] = __float_as_uint(p ? v5 : v4);   // (r,    kh*8+c+4)
                a2[kh][3] = __float_as_uint(p ? v7 : v6);   // (r+8,  kh*8+c+4)
            }

            float C2[2][4];
            #pragma unroll
            for (int nh = 0; nh < 2; ++nh) {
                C2[nh][0] = b2v[nh][0]; C2[nh][1] = b2v[nh][1];
                C2[nh][2] = b2v[nh][0]; C2[nh][3] = b2v[nh][1];
                mma_tf32(C2[nh], a2[0][0], a2[0][1], a2[0][2], a2[0][3],
                         w2b[0][nh][0], w2b[0][nh][1]);
                mma_tf32(C2[nh], a2[1][0], a2[1][1], a2[1][2], a2[1][3],
                         w2b[1][nh][0], w2b[1][nh][1]);
            }

            // epilogue: sp[T][rowhalf] += 0.5*w3[k] * tanh(C2)
            #pragma unroll
            for (int nh = 0; nh < 2; ++nh) {
                sp[T * 2 + 0] = fmaf(tanh_fast(C2[nh][0]), w3v[nh][0], sp[T * 2 + 0]);
                sp[T * 2 + 0] = fmaf(tanh_fast(C2[nh][1]), w3v[nh][1], sp[T * 2 + 0]);
                sp[T * 2 + 1] = fmaf(tanh_fast(C2[nh][2]), w3v[nh][0], sp[T * 2 + 1]);
                sp[T * 2 + 1] = fmaf(tanh_fast(C2[nh][3]), w3v[nh][1], sp[T * 2 + 1]);
            }
        }
    }
    #undef STAGE_J

    // ---- quad-reduce over c lanes and write out ----
    const float outC = *sOutC;
    #pragma unroll
    for (int T = 0; T < 4; ++T)
        #pragma unroll
        for (int s = 0; s < 2; ++s) {
            float vs = sp[T * 2 + s];
            vs += __shfl_xor_sync(0xffffffffu, vs, 1, 4);
            vs += __shfl_xor_sync(0xffffffffu, vs, 2, 4);
            if (c == 0) {
                const int b = bblk * 512 + wid * 64 + T * 16 + r + 8 * s;
                out[(size_t)b * NV + v] = vs + outC;
            }
        }
}

extern "C" void kernel_launch(void* const* d_in, const int* in_sizes, int n_in,
                              void* d_out, int out_size)
{
    const float* x      = (const float*)d_in[0];
    const int*   causal = (const int*)  d_in[1];
    const float* W1     = (const float*)d_in[2];
    const float* b1     = (const float*)d_in[3];
    const float* W2     = (const float*)d_in[4];
    const float* b2     = (const float*)d_in[5];
    const float* W3     = (const float*)d_in[6];
    const float* b3     = (const float*)d_in[7];
    float* out = (float*)d_out;

    static int configured = 0;
    if (!configured) {
        cudaFuncSetAttribute(additive_model_kernel,
                             cudaFuncAttributeMaxDynamicSharedMemorySize, SMEM_BYTES);
        configured = 1;
    }

    dim3 grid((BB / 512) * NV);   // 64 batch blocks * 16 variables = 1024 CTAs
    additive_model_kernel<<<grid, 256, SMEM_BYTES>>>(x, causal, W1, b1, W2, b2, W3, b3, out);
}

// round 14
// speedup vs baseline: 1.2626x; 1.0635x over previous
#include <cuda_runtime.h>
#include <cstdint>

// AdditiveModel on GB300 — R13: R12 tensor-core path with the C->A shuffle
// block DELETED via h-permutation. Permuting W1's output-channel order by
// pi(q) = (q>>1) + (q&1)*4 (per 8-block) makes conv1's C-fragment register
// layout identical to conv2's A-fragment layout (a0=c0, a1=c2, a2=c1, a3=c3,
// pure renaming). W2/b2/w3 staging UNCHANGED (contraction-slot h enumeration
// matches on both sides). x feeds mma as raw float bits (tf32 truncation,
// validated for t1 in R12). Removes 64 SHFL + 32 SEL + 32 CVT per j (~37%).
//
//   sigmoid(z) = 0.5*tanh(0.5 z) + 0.5
//   conv1: C1 = x @ (0.5*mask*W1_perm)^T + 0.5 b1_perm ; t1 = tanh(C1)
//   conv2: C2 = t1 @ (0.25*W2)^T + (0.25*rowsum(W2)+0.5 b2) ; t2 = tanh(C2)
//   out   = sum 0.5*w3*t2 + (b3 + 0.5*sum w3)

#define NV 16
#define BB 32768

__device__ __forceinline__ float tanh_fast(float x) {
    float t; asm("tanh.approx.f32 %0, %1;" : "=f"(t) : "f"(x)); return t;
}
__device__ __forceinline__ uint32_t f2tf32(float x) {
    uint32_t r; asm("cvt.rna.tf32.f32 %0, %1;" : "=r"(r) : "f"(x)); return r;
}
__device__ __forceinline__ void mma_tf32(float* d,
                                         uint32_t a0, uint32_t a1, uint32_t a2, uint32_t a3,
                                         uint32_t b0, uint32_t b1) {
    asm("mma.sync.aligned.m16n8k8.row.col.f32.tf32.tf32.f32 "
        "{%0,%1,%2,%3}, {%4,%5,%6,%7}, {%8,%9}, {%0,%1,%2,%3};"
        : "+f"(d[0]), "+f"(d[1]), "+f"(d[2]), "+f"(d[3])
        : "r"(a0), "r"(a1), "r"(a2), "r"(a3), "r"(b0), "r"(b1));
}

// h-permutation within each 8-block (high bit preserved)
__device__ __forceinline__ int permh(int q) {
    return (q & 8) | ((q & 7) >> 1) | ((q & 1) << 2);
}

// dynamic smem (floats):
//   sX [8 warps][2 slots][64 rows][18]   73728 B  (pitch-18 rows)
//   sW1 [16 j][16 l][16 hcol] tf32       16384 B  (0.5*mask folded, cols pi-permuted)
//   sW2t[16 j][16 h][16 k]   tf32        16384 B  (0.25 folded, UNpermuted)
//   sB1(perm)/sB2/sW3 [16 j][16]          3072 B
//   sOutC                                   16 B   total 109584 -> 112KB -> 2 CTAs
#define SMEM_BYTES (73728 + 16384 + 16384 + 1024 + 1024 + 1024 + 16)

__global__ __launch_bounds__(256, 2)
void additive_model_kernel(const float* __restrict__ x,
                           const int*   __restrict__ causal,
                           const float* __restrict__ W1,
                           const float* __restrict__ b1,
                           const float* __restrict__ W2,
                           const float* __restrict__ b2,
                           const float* __restrict__ W3,
                           const float* __restrict__ b3,
                           float* __restrict__ out)
{
    extern __shared__ float smem[];
    float*    sX    = smem;                      // 18432 floats
    uint32_t* sW1u  = (uint32_t*)(smem + 18432); // 4096
    uint32_t* sW2u  = sW1u + 4096;               // 4096
    float*    sB1   = (float*)(sW2u + 4096);     // 256
    float*    sB2   = sB1 + 256;
    float*    sW3   = sB2 + 256;
    float*    sOutC = sW3 + 256;

    const int v    = blockIdx.x & 15;
    const int bblk = blockIdx.x >> 4;
    const int tid  = threadIdx.x;
    const int wid  = tid >> 5;
    const int lane = tid & 31;
    const int r    = lane >> 2;   // 0..7
    const int c    = lane & 3;    // 0..3
    const int g0   = v * 16;

    // ---- stage weights (tf32-rounded, scales/mask folded, W1 cols permuted) ----
    #pragma unroll
    for (int i = 0; i < 16; ++i) {
        const int e = tid + i * 256;           // 0..4095
        const int j = e >> 8;
        const int a = (e >> 4) & 15;           // l for W1, h for W2t
        const int b = e & 15;                  // hcol for W1, k for W2t
        const int g = g0 + j;
        const float ms = (causal[g * 16 + a] != 0) ? 0.5f : 0.0f;
        sW1u[e] = f2tf32(ms * W1[(g * 16 + permh(b)) * 16 + a]);  // [j][l][hcol]=0.5*mask*W1[pi(hcol)][l]
        sW2u[e] = f2tf32(0.25f * W2[g * 256 + b * 16 + a]);       // [j][h][k] = 0.25*W2[k][h]
    }
    {   // biases + w3 (256 threads cover 16j x 16); b1 permuted like W1 cols
        const int j = tid >> 4, q = tid & 15;
        const int g = g0 + j;
        sB1[tid] = 0.5f * b1[g * 16 + permh(q)];
        float s0 = 0.f;
        #pragma unroll
        for (int h = 0; h < 16; ++h) s0 += W2[g * 256 + q * 16 + h];
        sB2[tid] = 0.25f * s0 + 0.5f * b2[g * 16 + q];
        sW3[tid] = 0.5f * W3[v * 256 + j * 16 + q];
    }
    if (tid == 0) {
        float cc = b3[v];
        #pragma unroll 1
        for (int m = 0; m < 256; ++m) cc += 0.5f * W3[v * 256 + m];
        *sOutC = cc;
    }
    __syncthreads();   // only CTA barrier

    // ---- warp-private x staging: 64 rows x 16 floats per j, pitch 18 ----
    const float* xw = x + (size_t)(bblk * 512 + wid * 64) * 4096 + g0 * 16;
    float* slotB = sX + wid * 2304;        // 2 slots * 1152 floats

    const int srow = lane >> 3;            // 0..3
    const int su   = lane & 7;             // 0..7
    const uint32_t dstage = (uint32_t)__cvta_generic_to_shared(
                                slotB + srow * 18 + su * 2);
    const float* sstage = xw + (size_t)srow * 4096 + su * 2;

    #define STAGE_J(j_)                                                               \
        do {                                                                          \
            const uint32_t _d = dstage + ((j_) & 1) * 4608;                           \
            const float*   _s = sstage + (j_) * 16;                                   \
            _Pragma("unroll")                                                         \
            for (int _i = 0; _i < 16; ++_i) {                                         \
                asm volatile("cp.async.ca.shared.global [%0], [%1], 8;"               \
                             :: "r"(_d + _i * 288),          /* 4 rows = 72 fl */     \
                                "l"(_s + (size_t)_i * 16384) /* 4 rows of x   */ );   \
            }                                                                         \
            asm volatile("cp.async.commit_group;");                                   \
        } while (0)

    STAGE_J(0);
    STAGE_J(1);

    float sp[8];   // [T][rowhalf] accumulators across j
    #pragma unroll
    for (int i = 0; i < 8; ++i) sp[i] = 0.0f;

    #pragma unroll 1
    for (int j = 0; j < 16; ++j) {
        if (j < 15) { asm volatile("cp.async.wait_group 1;" ::: "memory"); }
        else        { asm volatile("cp.async.wait_group 0;" ::: "memory"); }
        __syncwarp();

        const uint32_t* xs = (const uint32_t*)(slotB + (j & 1) * 1152);

        // ---- x A-fragments: raw float bits as tf32 (truncation) ----
        uint32_t xa[4][8];
        #pragma unroll
        for (int T = 0; T < 4; ++T) {
            #pragma unroll
            for (int kh = 0; kh < 2; ++kh) {
                const int base = (T * 16 + r) * 18 + kh * 8 + c;
                xa[T][kh * 4 + 0] = xs[base];
                xa[T][kh * 4 + 1] = xs[base + 8 * 18];
                xa[T][kh * 4 + 2] = xs[base + 4];
                xa[T][kh * 4 + 3] = xs[base + 8 * 18 + 4];
            }
        }

        if (j < 14) STAGE_J(j + 2);   // slot free after x loads

        // ---- weight B-fragments (warp-wide, reused across 4 tiles) ----
        uint32_t w1b[2][2][2], w2b[2][2][2];
        #pragma unroll
        for (int kh = 0; kh < 2; ++kh)
            #pragma unroll
            for (int nh = 0; nh < 2; ++nh) {
                const int o = j * 256 + (kh * 8 + c) * 16 + nh * 8 + r;
                w1b[kh][nh][0] = sW1u[o];
                w1b[kh][nh][1] = sW1u[o + 4 * 16];
                w2b[kh][nh][0] = sW2u[o];
                w2b[kh][nh][1] = sW2u[o + 4 * 16];
            }
        float b1v[2][2], b2v[2][2], w3v[2][2];
        #pragma unroll
        for (int nh = 0; nh < 2; ++nh) {
            b1v[nh][0] = sB1[j * 16 + nh * 8 + 2 * c];
            b1v[nh][1] = sB1[j * 16 + nh * 8 + 2 * c + 1];
            b2v[nh][0] = sB2[j * 16 + nh * 8 + 2 * c];
            b2v[nh][1] = sB2[j * 16 + nh * 8 + 2 * c + 1];
            w3v[nh][0] = sW3[j * 16 + nh * 8 + 2 * c];
            w3v[nh][1] = sW3[j * 16 + nh * 8 + 2 * c + 1];
        }

        // ---- per 16-batch tile: conv1 mma -> tanh (reg-renamed A) -> conv2 mma -> epi ----
        #pragma unroll
        for (int T = 0; T < 4; ++T) {
            float C1[2][4];
            #pragma unroll
            for (int nh = 0; nh < 2; ++nh) {
                C1[nh][0] = b1v[nh][0]; C1[nh][1] = b1v[nh][1];
                C1[nh][2] = b1v[nh][0]; C1[nh][3] = b1v[nh][1];
                mma_tf32(C1[nh], xa[T][0], xa[T][1], xa[T][2], xa[T][3],
                         w1b[0][nh][0], w1b[0][nh][1]);
                mma_tf32(C1[nh], xa[T][4], xa[T][5], xa[T][6], xa[T][7],
                         w1b[1][nh][0], w1b[1][nh][1]);
            }

            // tanh in place; C-layout IS conv2 A-layout after pi-permutation:
            // a0 = c0 (r, h=kh*8+c), a1 = c2 (r+8, c), a2 = c1 (r, c+4), a3 = c3
            uint32_t a2f[2][4];
            #pragma unroll
            for (int kh = 0; kh < 2; ++kh) {
                a2f[kh][0] = __float_as_uint(tanh_fast(C1[kh][0]));
                a2f[kh][1] = __float_as_uint(tanh_fast(C1[kh][2]));
                a2f[kh][2] = __float_as_uint(tanh_fast(C1[kh][1]));
                a2f[kh][3] = __float_as_uint(tanh_fast(C1[kh][3]));
            }

            float C2[2][4];
            #pragma unroll
            for (int nh = 0; nh < 2; ++nh) {
                C2[nh][0] = b2v[nh][0]; C2[nh][1] = b2v[nh][1];
                C2[nh][2] = b2v[nh][0]; C2[nh][3] = b2v[nh][1];
                mma_tf32(C2[nh], a2f[0][0], a2f[0][1], a2f[0][2], a2f[0][3],
                         w2b[0][nh][0], w2b[0][nh][1]);
                mma_tf32(C2[nh], a2f[1][0], a2f[1][1], a2f[1][2], a2f[1][3],
                         w2b[1][nh][0], w2b[1][nh][1]);
            }

            // epilogue: sp[T][rowhalf] += 0.5*w3[k] * tanh(C2)
            #pragma unroll
            for (int nh = 0; nh < 2; ++nh) {
                sp[T * 2 + 0] = fmaf(tanh_fast(C2[nh][0]), w3v[nh][0], sp[T * 2 + 0]);
                sp[T * 2 + 0] = fmaf(tanh_fast(C2[nh][1]), w3v[nh][1], sp[T * 2 + 0]);
                sp[T * 2 + 1] = fmaf(tanh_fast(C2[nh][2]), w3v[nh][0], sp[T * 2 + 1]);
                sp[T * 2 + 1] = fmaf(tanh_fast(C2[nh][3]), w3v[nh][1], sp[T * 2 + 1]);
            }
        }
    }
    #undef STAGE_J

    // ---- quad-reduce over c lanes and write out ----
    const float outC = *sOutC;
    #pragma unroll
    for (int T = 0; T < 4; ++T)
        #pragma unroll
        for (int s = 0; s < 2; ++s) {
            float vs = sp[T * 2 + s];
            vs += __shfl_xor_sync(0xffffffffu, vs, 1, 4);
            vs += __shfl_xor_sync(0xffffffffu, vs, 2, 4);
            if (c == 0) {
                const int b = bblk * 512 + wid * 64 + T * 16 + r + 8 * s;
                out[(size_t)b * NV + v] = vs + outC;
            }
        }
}

extern "C" void kernel_launch(void* const* d_in, const int* in_sizes, int n_in,
                              void* d_out, int out_size)
{
    const float* x      = (const float*)d_in[0];
    const int*   causal = (const int*)  d_in[1];
    const float* W1     = (const float*)d_in[2];
    const float* b1     = (const float*)d_in[3];
    const float* W2     = (const float*)d_in[4];
    const float* b2     = (const float*)d_in[5];
    const float* W3     = (const float*)d_in[6];
    const float* b3     = (const float*)d_in[7];
    float* out = (float*)d_out;

    static int configured = 0;
    if (!configured) {
        cudaFuncSetAttribute(additive_model_kernel,
                             cudaFuncAttributeMaxDynamicSharedMemorySize, SMEM_BYTES);
        configured = 1;
    }

    dim3 grid((BB / 512) * NV);   // 64 batch blocks * 16 variables = 1024 CTAs
    additive_model_kernel<<<grid, 256, SMEM_BYTES>>>(x, causal, W1, b1, W2, b2, W3, b3, out);
}